// round 1
// baseline (speedup 1.0000x reference)
#include <cuda_runtime.h>
#include <math.h>

#define BB    128
#define NQv   32
#define NWv   12
#define NKv   64
#define EMBv  300
#define FEATv 2048
#define EPSV  1e-5f

// ---------------- scratch (device globals; no allocation allowed) -------------
__device__ float g_kemb[BB * NKv * EMBv];    // [8192, 300]
__device__ float g_p0  [BB * NQv * EMBv];    // [4096, 300] pre-linear p_emb
__device__ float g_pemb[BB * NQv * EMBv];    // [4096, 300] post-linear p_emb
__device__ float g_Wc  [EMBv * EMBv];        // Wp + EPS*Wm
__device__ float g_bc  [EMBv];               // bp + EPS*bm

// ---------------- tiny: combine Wp/Wm and biases ------------------------------
__global__ void combine_kernel(const float* __restrict__ Wp, const float* __restrict__ bp,
                               const float* __restrict__ Wm, const float* __restrict__ bm)
{
    int i = blockIdx.x * blockDim.x + threadIdx.x;
    if (i < EMBv * EMBv) g_Wc[i] = Wp[i] + EPSV * Wm[i];
    if (i < EMBv)        g_bc[i] = bp[i] + EPSV * bm[i];
}

// ---------------- target = eye(B) ---------------------------------------------
__global__ void eye_kernel(float* __restrict__ target)
{
    int i = blockIdx.x * blockDim.x + threadIdx.x;
    if (i < BB * BB) target[i] = ((i / BB) == (i % BB)) ? 1.0f : 0.0f;
}

// ---------------- generic C = A * B^T tiled SGEMM -----------------------------
// A: [M, K] row-major (lda), B: [N, K] row-major (ldb)  (both K-contiguous)
// Tile 128x64, BK=32, 128 threads, 8x8 micro-tiles.
// mode 0: A=Aext(feature), B=Bext(Wf), out=g_kemb, epi: + wv[label[m]][n] + bf[n]
// mode 1: A=g_p0, B=g_Wc, out=g_pemb, epi: + g_bc[n]
__global__ __launch_bounds__(128) void gemm_tn(
    const float* __restrict__ Aext, int lda,
    const float* __restrict__ Bext, int ldb,
    int M, int N, int K, int mode,
    const float* __restrict__ bias,         // bf (mode 0)
    const float* __restrict__ gtab,         // wv (mode 0)
    const int*   __restrict__ gidx)         // label (mode 0)
{
    __shared__ float As[32][128];
    __shared__ float Bs[32][64];

    const float* A  = (mode == 1) ? g_p0  : Aext;
    const float* Bm = (mode == 1) ? g_Wc  : Bext;
    float*      Co  = (mode == 1) ? g_pemb : g_kemb;
    const float* bv = (mode == 1) ? g_bc  : bias;

    const int m0 = blockIdx.y * 128;
    const int n0 = blockIdx.x * 64;
    const int t  = threadIdx.x;
    const int ty = t >> 3;   // 0..15  (rows ty + 16*i)
    const int tx = t & 7;    // 0..7   (cols tx + 8*j)

    float acc[8][8];
#pragma unroll
    for (int i = 0; i < 8; i++)
#pragma unroll
        for (int j = 0; j < 8; j++) acc[i][j] = 0.0f;

    for (int k0 = 0; k0 < K; k0 += 32) {
        // load A tile: 128 rows x 32 k (8 float4 per row). thread t owns row t.
#pragma unroll
        for (int p = 0; p < 8; p++) {
            int kk = k0 + p * 4;
            float4 v = make_float4(0.f, 0.f, 0.f, 0.f);
            if (kk < K) v = *(const float4*)(A + (size_t)(m0 + t) * lda + kk);
            As[p * 4 + 0][t] = v.x;
            As[p * 4 + 1][t] = v.y;
            As[p * 4 + 2][t] = v.z;
            As[p * 4 + 3][t] = v.w;
        }
        // load B tile: 64 rows x 32 k
#pragma unroll
        for (int p = 0; p < 4; p++) {
            int idx = p * 128 + t;
            int r  = idx & 63;
            int c4 = idx >> 6;
            int kk = k0 + c4 * 4;
            int gn = n0 + r;
            float4 v = make_float4(0.f, 0.f, 0.f, 0.f);
            if (kk < K && gn < N) v = *(const float4*)(Bm + (size_t)gn * ldb + kk);
            Bs[c4 * 4 + 0][r] = v.x;
            Bs[c4 * 4 + 1][r] = v.y;
            Bs[c4 * 4 + 2][r] = v.z;
            Bs[c4 * 4 + 3][r] = v.w;
        }
        __syncthreads();

#pragma unroll
        for (int kk = 0; kk < 32; kk++) {
            float a[8], b[8];
#pragma unroll
            for (int i = 0; i < 8; i++) a[i] = As[kk][ty + 16 * i];
#pragma unroll
            for (int j = 0; j < 8; j++) b[j] = Bs[kk][tx + 8 * j];
#pragma unroll
            for (int i = 0; i < 8; i++)
#pragma unroll
                for (int j = 0; j < 8; j++) acc[i][j] += a[i] * b[j];
        }
        __syncthreads();
    }

#pragma unroll
    for (int i = 0; i < 8; i++) {
        int gm = m0 + ty + 16 * i;
        const float* grow = (mode == 0) ? (gtab + (size_t)gidx[gm] * EMBv) : nullptr;
#pragma unroll
        for (int j = 0; j < 8; j++) {
            int gn = n0 + tx + 8 * j;
            if (gn < N) {
                float c = acc[i][j] + bv[gn];
                if (mode == 0) c += grow[gn];
                Co[(size_t)gm * N + gn] = c;
            }
        }
    }
}

// ---------------- per-(b,q): word attention -> p0 -----------------------------
// 384 threads = 12 warps; warp w handles word w. Each lane owns objects k=lane, lane+32.
__global__ __launch_bounds__(384) void p0_kernel(const int* __restrict__ query,
                                                 const float* __restrict__ wv)
{
    __shared__ float Qs[NWv][304];
    __shared__ int   qi[NWv];
    __shared__ float qma[NWv];
    __shared__ float qnorm[NWv];

    const int b  = blockIdx.x >> 5;
    const int qy = blockIdx.x & 31;
    const int t  = threadIdx.x;
    const int warp = t >> 5, lane = t & 31;

    if (t < NWv) qi[t] = query[(b * NQv + qy) * NWv + t];
    __syncthreads();

    // gather q_emb rows: 12 * 75 float4 = 900 loads
#pragma unroll
    for (int p = 0; p < 3; p++) {
        int idx = p * 384 + t;
        if (idx < 900) {
            int r = idx / 75, c = idx % 75;
            float4 v = *(const float4*)(wv + (size_t)qi[r] * EMBv + c * 4);
            *(float4*)&Qs[r][c * 4] = v;
        }
    }
    __syncthreads();

    // S[w][k] = Q[w] . kemb[b,k] * (1/sqrt(EMB))
    const float* k0p = g_kemb + (size_t)(b * NKv + lane) * EMBv;
    const float* k1p = g_kemb + (size_t)(b * NKv + lane + 32) * EMBv;
    float acc0 = 0.f, acc1 = 0.f;
#pragma unroll 5
    for (int d4 = 0; d4 < 75; d4++) {
        float4 q4 = *(const float4*)&Qs[warp][d4 * 4];
        float4 a4 = *(const float4*)(k0p + d4 * 4);
        float4 c4 = *(const float4*)(k1p + d4 * 4);
        acc0 += q4.x * a4.x + q4.y * a4.y + q4.z * a4.z + q4.w * a4.w;
        acc1 += q4.x * c4.x + q4.y * c4.y + q4.z * c4.z + q4.w * c4.w;
    }
    const float scale = rsqrtf((float)EMBv);
    acc0 *= scale; acc1 *= scale;

    // max over 64 objects, then sum of exp -> q_max_att[w] = 1/sumexp
    float mx = fmaxf(acc0, acc1);
#pragma unroll
    for (int o = 16; o; o >>= 1) mx = fmaxf(mx, __shfl_xor_sync(0xffffffffu, mx, o));
    float se = __expf(acc0 - mx) + __expf(acc1 - mx);
#pragma unroll
    for (int o = 16; o; o >>= 1) se += __shfl_xor_sync(0xffffffffu, se, o);
    if (lane == 0) qma[warp] = 1.0f / se;
    __syncthreads();

    // softmax over 12 words (warp 0)
    if (warp == 0) {
        float v = (lane < NWv) ? qma[lane] : -1e30f;
        float m2 = v;
#pragma unroll
        for (int o = 16; o; o >>= 1) m2 = fmaxf(m2, __shfl_xor_sync(0xffffffffu, m2, o));
        float e = (lane < NWv) ? __expf(v - m2) : 0.f;
        float s2 = e;
#pragma unroll
        for (int o = 16; o; o >>= 1) s2 += __shfl_xor_sync(0xffffffffu, s2, o);
        if (lane < NWv) qnorm[lane] = e / s2;
    }
    __syncthreads();

    // p0[d] = sum_w qnorm[w] * Q[w][d]
    if (t < EMBv) {
        float s = 0.f;
#pragma unroll
        for (int w = 0; w < NWv; w++) s += qnorm[w] * Qs[w][t];
        g_p0[(size_t)(b * NQv + qy) * EMBv + t] = s;
    }
}

// ---------------- attmap GEMM + fused softmax/max/sum epilogue ----------------
// C tile = pemb rows [m0,m0+128) x kemb rows [n0,n0+64): exactly 4 (b,a) blocks.
__global__ __launch_bounds__(128) void attmap_kernel(
    float* __restrict__ logits, float* __restrict__ attsum,
    const int* __restrict__ num_query)
{
    union Sm {
        struct { float As[32][128]; float Bs[32][64]; } mm;
        struct { float Cs[128][65]; float rinv[128]; } ep;
    };
    __shared__ Sm sm;

    const int m0 = blockIdx.y * 128;   // pemb row tile (32 tiles)
    const int n0 = blockIdx.x * 64;    // kemb row tile (128 tiles)
    const int t  = threadIdx.x;
    const int ty = t >> 3, tx = t & 7;

    float acc[8][8];
#pragma unroll
    for (int i = 0; i < 8; i++)
#pragma unroll
        for (int j = 0; j < 8; j++) acc[i][j] = 0.0f;

    const int K = EMBv;
    for (int k0 = 0; k0 < K; k0 += 32) {
#pragma unroll
        for (int p = 0; p < 8; p++) {
            int kk = k0 + p * 4;
            float4 v = make_float4(0.f, 0.f, 0.f, 0.f);
            if (kk < K) v = *(const float4*)(g_pemb + (size_t)(m0 + t) * EMBv + kk);
            sm.mm.As[p * 4 + 0][t] = v.x;
            sm.mm.As[p * 4 + 1][t] = v.y;
            sm.mm.As[p * 4 + 2][t] = v.z;
            sm.mm.As[p * 4 + 3][t] = v.w;
        }
#pragma unroll
        for (int p = 0; p < 4; p++) {
            int idx = p * 128 + t;
            int r = idx & 63, c4 = idx >> 6;
            int kk = k0 + c4 * 4;
            float4 v = make_float4(0.f, 0.f, 0.f, 0.f);
            if (kk < K) v = *(const float4*)(g_kemb + (size_t)(n0 + r) * EMBv + kk);
            sm.mm.Bs[c4 * 4 + 0][r] = v.x;
            sm.mm.Bs[c4 * 4 + 1][r] = v.y;
            sm.mm.Bs[c4 * 4 + 2][r] = v.z;
            sm.mm.Bs[c4 * 4 + 3][r] = v.w;
        }
        __syncthreads();
#pragma unroll
        for (int kk = 0; kk < 32; kk++) {
            float a[8], b[8];
#pragma unroll
            for (int i = 0; i < 8; i++) a[i] = sm.mm.As[kk][ty + 16 * i];
#pragma unroll
            for (int j = 0; j < 8; j++) b[j] = sm.mm.Bs[kk][tx + 8 * j];
#pragma unroll
            for (int i = 0; i < 8; i++)
#pragma unroll
                for (int j = 0; j < 8; j++) acc[i][j] += a[i] * b[j];
        }
        __syncthreads();
    }

    // stash C tile in smem (union reuse is safe: all operand reads are done)
#pragma unroll
    for (int i = 0; i < 8; i++)
#pragma unroll
        for (int j = 0; j < 8; j++)
            sm.ep.Cs[ty + 16 * i][tx + 8 * j] = acc[i][j];
    __syncthreads();

    const int warp = t >> 5, lane = t & 31;
    // warp handles (b,a) block: rows warp*32..+31, all 64 cols. lane = row q.
    float* row = sm.ep.Cs[warp * 32 + lane];
    float mx = -1e30f;
#pragma unroll
    for (int v = 0; v < 64; v++) mx = fmaxf(mx, row[v]);
    float se = 0.f;
#pragma unroll
    for (int v = 0; v < 64; v++) {
        float e = __expf(row[v] - mx);
        se += e;
        row[v] = e;
    }
    sm.ep.rinv[warp * 32 + lane] = 1.0f / se;

    // logits[b][a] = sum_q max_v(C) / num_query[b]
    float s = mx;
#pragma unroll
    for (int o = 16; o; o >>= 1) s += __shfl_xor_sync(0xffffffffu, s, o);
    const int b = (m0 >> 5) + warp;
    const int a = n0 >> 6;
    if (lane == 0) logits[b * BB + a] = s / (float)num_query[b];
    __syncthreads();

    // att_obj_sum[b][a][v] = sum_q exp(C-max)/sumexp
#pragma unroll
    for (int h = 0; h < 2; h++) {
        int v = lane + 32 * h;
        float s2 = 0.f;
#pragma unroll
        for (int q2 = 0; q2 < 32; q2++)
            s2 += sm.ep.Cs[warp * 32 + q2][v] * sm.ep.rinv[warp * 32 + q2];
        attsum[((size_t)b * BB + a) * NKv + v] = s2;
    }
}

// ---------------- launch ------------------------------------------------------
extern "C" void kernel_launch(void* const* d_in, const int* in_sizes, int n_in,
                              void* d_out, int out_size)
{
    const int*   query     = (const int*)  d_in[1];
    const int*   label     = (const int*)  d_in[2];
    const float* feature   = (const float*)d_in[3];
    const int*   num_query = (const int*)  d_in[7];
    const float* wv        = (const float*)d_in[8];
    const float* Wp        = (const float*)d_in[9];
    const float* bp        = (const float*)d_in[10];
    const float* Wm        = (const float*)d_in[11];
    const float* bm        = (const float*)d_in[12];
    const float* Wf        = (const float*)d_in[13];
    const float* bf        = (const float*)d_in[14];

    float* out    = (float*)d_out;
    float* logits = out;                    // [B,B]
    float* target = out + BB * BB;          // [B,B]
    float* attsum = out + 2 * BB * BB;      // [B,B,NK]

    // W' = Wp + EPS*Wm, b' = bp + EPS*bm
    combine_kernel<<<(EMBv * EMBv + 255) / 256, 256>>>(Wp, bp, Wm, bm);
    // k_emb = feature @ Wf^T + wv[label] + bf   (M=8192, N=300, K=2048)
    gemm_tn<<<dim3(5, 64), 128>>>(feature, FEATv, Wf, FEATv,
                                  BB * NKv, EMBv, FEATv, 0, bf, wv, label);
    // word attention -> p0  (one CTA per (b,q))
    p0_kernel<<<BB * NQv, 384>>>(query, wv);
    // p_emb = p0 @ W'^T + b'   (M=4096, N=300, K=300)
    gemm_tn<<<dim3(5, 32), 128>>>(nullptr, EMBv, nullptr, EMBv,
                                  BB * NQv, EMBv, EMBv, 1, nullptr, nullptr, nullptr);
    // attmap GEMM + fused reductions (grid: 128 a-tiles x 32 row-tiles)
    attmap_kernel<<<dim3(BB, 32), 128>>>(logits, attsum, num_query);
    // target = eye(B)
    eye_kernel<<<(BB * BB + 255) / 256, 256>>>(target);
}

// round 3
// speedup vs baseline: 1.0384x; 1.0384x over previous
#include <cuda_runtime.h>
#include <math.h>
#include <stdint.h>

#define BB    128
#define NQv   32
#define NWv   12
#define NKv   64
#define EMBv  300
#define KP    320      // padded K (multiple of 32 floats); padding stays zero
#define FEATv 2048
#define EPSV  1e-5f

#define AS_LD 136      // stride ≡ 8 (mod 32) -> conflict-free fragment loads
#define BS_LD 72

// ---------------- scratch (device globals; zero-initialized at load) ----------
__device__ float g_kemb [BB * NKv * KP];      // tf32-rounded k_emb, cols 300..319 = 0
__device__ float g_p0   [BB * NQv * EMBv];
__device__ float g_pembr[BB * NQv * KP];      // tf32-rounded p_emb, cols 300..319 = 0
__device__ float g_Wc   [EMBv * EMBv];        // rna(Wp + EPS*Wm)
__device__ float g_bc   [EMBv];

// ---------------- helpers -----------------------------------------------------
__device__ __forceinline__ float rna_tf32(float x) {
    uint32_t u; asm("cvt.rna.tf32.f32 %0, %1;" : "=r"(u) : "f"(x));
    return __uint_as_float(u);
}

__device__ __forceinline__ void mma_tf32(float* d, const float* a, const float* b) {
    asm volatile(
        "mma.sync.aligned.m16n8k8.row.col.f32.tf32.tf32.f32 "
        "{%0,%1,%2,%3}, {%4,%5,%6,%7}, {%8,%9}, {%0,%1,%2,%3};\n"
        : "+f"(d[0]), "+f"(d[1]), "+f"(d[2]), "+f"(d[3])
        : "r"(__float_as_uint(a[0])), "r"(__float_as_uint(a[1])),
          "r"(__float_as_uint(a[2])), "r"(__float_as_uint(a[3])),
          "r"(__float_as_uint(b[0])), "r"(__float_as_uint(b[1])));
}

// ---------------- small kernels ------------------------------------------------
__global__ void combine_kernel(const float* __restrict__ Wp, const float* __restrict__ bp,
                               const float* __restrict__ Wm, const float* __restrict__ bm)
{
    int i = blockIdx.x * blockDim.x + threadIdx.x;
    if (i < EMBv * EMBv) g_Wc[i] = rna_tf32(Wp[i] + EPSV * Wm[i]);
    if (i < EMBv)        g_bc[i] = bp[i] + EPSV * bm[i];
}

__global__ void eye_kernel(float* __restrict__ target)
{
    int i = blockIdx.x * blockDim.x + threadIdx.x;
    if (i < BB * BB) target[i] = ((i / BB) == (i % BB)) ? 1.0f : 0.0f;
}

// ---------------- generic tf32 MMA GEMM: C = A * B^T --------------------------
// Tile 128x64, 256 threads, warp grid 4(M)x2(N), warp tile 32x32, BK=32.
// mode 0 (kemb): epi out = rna(C + bias[n] + wv[label[m]][n]), out stride KP
// mode 1 (pemb): epi out = rna(C + bias[n]),                   out stride KP
__global__ __launch_bounds__(256) void mma_gemm_kernel(
    const float* __restrict__ A, int lda, int aF4,
    const float* __restrict__ Bp, int ldb, int bRows, int bF4,
    int nChunks, int mode, int doRoundA, int doRoundB,
    const float* __restrict__ bias,
    const float* __restrict__ wv, const int* __restrict__ label,
    float* __restrict__ out)
{
    __shared__ float As[32 * AS_LD];
    __shared__ float Bs[32 * BS_LD];

    const int m0 = blockIdx.y * 128;
    const int n0 = blockIdx.x * 64;
    const int t  = threadIdx.x;
    const int wid = t >> 5, lane = t & 31;
    const int wm = wid & 3, wn = wid >> 2;     // 4 x 2 warp grid
    const int g = lane >> 2, tid4 = lane & 3;

    float acc[2][4][4];
#pragma unroll
    for (int i = 0; i < 2; i++)
#pragma unroll
        for (int j = 0; j < 4; j++)
#pragma unroll
            for (int r = 0; r < 4; r++) acc[i][j][r] = 0.0f;

    for (int c = 0; c < nChunks; c++) {
        // stage A: 128 rows x 8 float4
#pragma unroll
        for (int it = 0; it < 4; it++) {
            int idx = it * 256 + t;
            int m = idx >> 3, p = idx & 7;
            int f4 = c * 8 + p;
            float4 v = make_float4(0.f, 0.f, 0.f, 0.f);
            if (f4 < aF4) v = *(const float4*)(A + (size_t)(m0 + m) * lda + f4 * 4);
            if (doRoundA) { v.x = rna_tf32(v.x); v.y = rna_tf32(v.y);
                            v.z = rna_tf32(v.z); v.w = rna_tf32(v.w); }
            As[(p * 4 + 0) * AS_LD + m] = v.x;
            As[(p * 4 + 1) * AS_LD + m] = v.y;
            As[(p * 4 + 2) * AS_LD + m] = v.z;
            As[(p * 4 + 3) * AS_LD + m] = v.w;
        }
        // stage B: 64 rows x 8 float4
#pragma unroll
        for (int it = 0; it < 2; it++) {
            int idx = it * 256 + t;
            int r = idx >> 3, p = idx & 7;
            int f4 = c * 8 + p;
            float4 v = make_float4(0.f, 0.f, 0.f, 0.f);
            if (f4 < bF4 && (n0 + r) < bRows)
                v = *(const float4*)(Bp + (size_t)(n0 + r) * ldb + f4 * 4);
            if (doRoundB) { v.x = rna_tf32(v.x); v.y = rna_tf32(v.y);
                            v.z = rna_tf32(v.z); v.w = rna_tf32(v.w); }
            Bs[(p * 4 + 0) * BS_LD + r] = v.x;
            Bs[(p * 4 + 1) * BS_LD + r] = v.y;
            Bs[(p * 4 + 2) * BS_LD + r] = v.z;
            Bs[(p * 4 + 3) * BS_LD + r] = v.w;
        }
        __syncthreads();

#pragma unroll
        for (int ks = 0; ks < 4; ks++) {
            const int kb = ks * 8;
            float a[2][4];
#pragma unroll
            for (int i = 0; i < 2; i++) {
                int row = wm * 32 + i * 16 + g;
                a[i][0] = As[(kb + tid4) * AS_LD + row];
                a[i][1] = As[(kb + tid4) * AS_LD + row + 8];
                a[i][2] = As[(kb + tid4 + 4) * AS_LD + row];
                a[i][3] = As[(kb + tid4 + 4) * AS_LD + row + 8];
            }
            float b[4][2];
#pragma unroll
            for (int j = 0; j < 4; j++) {
                int col = wn * 32 + j * 8 + g;
                b[j][0] = Bs[(kb + tid4) * BS_LD + col];
                b[j][1] = Bs[(kb + tid4 + 4) * BS_LD + col];
            }
#pragma unroll
            for (int i = 0; i < 2; i++)
#pragma unroll
                for (int j = 0; j < 4; j++) mma_tf32(acc[i][j], a[i], b[j]);
        }
        __syncthreads();
    }

    // epilogue -> global (tf32-rounded, stride KP)
#pragma unroll
    for (int i = 0; i < 2; i++) {
#pragma unroll
        for (int rh = 0; rh < 2; rh++) {
            int gm = m0 + wm * 32 + i * 16 + g + rh * 8;
            const float* wrow = (mode == 0) ? (wv + (size_t)label[gm] * EMBv) : nullptr;
#pragma unroll
            for (int j = 0; j < 4; j++) {
                int gn = n0 + wn * 32 + j * 8 + 2 * tid4;
#pragma unroll
                for (int q = 0; q < 2; q++) {
                    int n = gn + q;
                    if (n < EMBv) {
                        float v = acc[i][j][rh * 2 + q] + bias[n];
                        if (mode == 0) v += wrow[n];
                        out[(size_t)gm * KP + n] = rna_tf32(v);
                    }
                }
            }
        }
    }
}

// ---------------- per-(b,q): word attention -> p0 (scalar fp32) ---------------
__global__ __launch_bounds__(384) void p0_kernel(const int* __restrict__ query,
                                                 const float* __restrict__ wv)
{
    __shared__ float Qs[NWv][304];
    __shared__ int   qi[NWv];
    __shared__ float qma[NWv];
    __shared__ float qnorm[NWv];

    const int b  = blockIdx.x >> 5;
    const int qy = blockIdx.x & 31;
    const int t  = threadIdx.x;
    const int warp = t >> 5, lane = t & 31;

    if (t < NWv) qi[t] = query[(b * NQv + qy) * NWv + t];
    __syncthreads();
#pragma unroll
    for (int p = 0; p < 3; p++) {
        int idx = p * 384 + t;
        if (idx < 900) {
            int r = idx / 75, c = idx % 75;
            *(float4*)&Qs[r][c * 4] = *(const float4*)(wv + (size_t)qi[r] * EMBv + c * 4);
        }
    }
    __syncthreads();

    const float* k0p = g_kemb + (size_t)(b * NKv + lane) * KP;
    const float* k1p = g_kemb + (size_t)(b * NKv + lane + 32) * KP;
    float acc0 = 0.f, acc1 = 0.f;
#pragma unroll 5
    for (int d4 = 0; d4 < 75; d4++) {
        float4 q4 = *(const float4*)&Qs[warp][d4 * 4];
        float4 a4 = *(const float4*)(k0p + d4 * 4);
        float4 c4 = *(const float4*)(k1p + d4 * 4);
        acc0 += q4.x * a4.x + q4.y * a4.y + q4.z * a4.z + q4.w * a4.w;
        acc1 += q4.x * c4.x + q4.y * c4.y + q4.z * c4.z + q4.w * c4.w;
    }
    const float scale = rsqrtf((float)EMBv);
    acc0 *= scale; acc1 *= scale;

    float mx = fmaxf(acc0, acc1);
#pragma unroll
    for (int o = 16; o; o >>= 1) mx = fmaxf(mx, __shfl_xor_sync(0xffffffffu, mx, o));
    float se = __expf(acc0 - mx) + __expf(acc1 - mx);
#pragma unroll
    for (int o = 16; o; o >>= 1) se += __shfl_xor_sync(0xffffffffu, se, o);
    if (lane == 0) qma[warp] = 1.0f / se;
    __syncthreads();

    if (warp == 0) {
        float v = (lane < NWv) ? qma[lane] : -1e30f;
        float m2 = v;
#pragma unroll
        for (int o = 16; o; o >>= 1) m2 = fmaxf(m2, __shfl_xor_sync(0xffffffffu, m2, o));
        float e = (lane < NWv) ? __expf(v - m2) : 0.f;
        float s2 = e;
#pragma unroll
        for (int o = 16; o; o >>= 1) s2 += __shfl_xor_sync(0xffffffffu, s2, o);
        if (lane < NWv) qnorm[lane] = e / s2;
    }
    __syncthreads();

    if (t < EMBv) {
        float s = 0.f;
#pragma unroll
        for (int w = 0; w < NWv; w++) s += qnorm[w] * Qs[w][t];
        g_p0[(size_t)(b * NQv + qy) * EMBv + t] = s;
    }
}

// ---------------- attmap tf32 MMA + fused softmax/max/sum ---------------------
// Tile: 128 pemb rows (4 b-blocks) x 64 kemb rows (1 a-block), K = 320 unguarded.
__global__ __launch_bounds__(256) void attmap_mma_kernel(
    float* __restrict__ logits, float* __restrict__ attsum,
    const int* __restrict__ num_query)
{
    __shared__ union {
        struct { float As[32 * AS_LD]; float Bs[32 * BS_LD]; } mm;
        float Cs[128 * 65];
    } sm;

    const int m0 = blockIdx.y * 128;
    const int n0 = blockIdx.x * 64;
    const int t  = threadIdx.x;
    const int wid = t >> 5, lane = t & 31;
    const int wm = wid & 3, wn = wid >> 2;
    const int g = lane >> 2, tid4 = lane & 3;

    float acc[2][4][4];
#pragma unroll
    for (int i = 0; i < 2; i++)
#pragma unroll
        for (int j = 0; j < 4; j++)
#pragma unroll
            for (int r = 0; r < 4; r++) acc[i][j][r] = 0.0f;

    for (int c = 0; c < KP / 32; c++) {
#pragma unroll
        for (int it = 0; it < 4; it++) {
            int idx = it * 256 + t;
            int m = idx >> 3, p = idx & 7;
            float4 v = *(const float4*)(g_pembr + (size_t)(m0 + m) * KP + (c * 8 + p) * 4);
            sm.mm.As[(p * 4 + 0) * AS_LD + m] = v.x;
            sm.mm.As[(p * 4 + 1) * AS_LD + m] = v.y;
            sm.mm.As[(p * 4 + 2) * AS_LD + m] = v.z;
            sm.mm.As[(p * 4 + 3) * AS_LD + m] = v.w;
        }
#pragma unroll
        for (int it = 0; it < 2; it++) {
            int idx = it * 256 + t;
            int r = idx >> 3, p = idx & 7;
            float4 v = *(const float4*)(g_kemb + (size_t)(n0 + r) * KP + (c * 8 + p) * 4);
            sm.mm.Bs[(p * 4 + 0) * BS_LD + r] = v.x;
            sm.mm.Bs[(p * 4 + 1) * BS_LD + r] = v.y;
            sm.mm.Bs[(p * 4 + 2) * BS_LD + r] = v.z;
            sm.mm.Bs[(p * 4 + 3) * BS_LD + r] = v.w;
        }
        __syncthreads();

#pragma unroll
        for (int ks = 0; ks < 4; ks++) {
            const int kb = ks * 8;
            float a[2][4];
#pragma unroll
            for (int i = 0; i < 2; i++) {
                int row = wm * 32 + i * 16 + g;
                a[i][0] = sm.mm.As[(kb + tid4) * AS_LD + row];
                a[i][1] = sm.mm.As[(kb + tid4) * AS_LD + row + 8];
                a[i][2] = sm.mm.As[(kb + tid4 + 4) * AS_LD + row];
                a[i][3] = sm.mm.As[(kb + tid4 + 4) * AS_LD + row + 8];
            }
            float b[4][2];
#pragma unroll
            for (int j = 0; j < 4; j++) {
                int col = wn * 32 + j * 8 + g;
                b[j][0] = sm.mm.Bs[(kb + tid4) * BS_LD + col];
                b[j][1] = sm.mm.Bs[(kb + tid4 + 4) * BS_LD + col];
            }
#pragma unroll
            for (int i = 0; i < 2; i++)
#pragma unroll
                for (int j = 0; j < 4; j++) mma_tf32(acc[i][j], a[i], b[j]);
        }
        __syncthreads();
    }

    // C -> smem [128][65]
#pragma unroll
    for (int i = 0; i < 2; i++) {
        int r = wm * 32 + i * 16 + g;
#pragma unroll
        for (int j = 0; j < 4; j++) {
            int cb = wn * 32 + j * 8 + 2 * tid4;
            sm.Cs[r * 65 + cb]           = acc[i][j][0];
            sm.Cs[r * 65 + cb + 1]       = acc[i][j][1];
            sm.Cs[(r + 8) * 65 + cb]     = acc[i][j][2];
            sm.Cs[(r + 8) * 65 + cb + 1] = acc[i][j][3];
        }
    }
    __syncthreads();

    const int a_idx = n0 >> 6;
    if (wid < 4) {
        // warp = b-block, lane = row q
        float* row = &sm.Cs[(wid * 32 + lane) * 65];
        float mx = -1e30f;
#pragma unroll
        for (int v = 0; v < 64; v++) mx = fmaxf(mx, row[v]);

        const int b = (m0 >> 5) + wid;
        float s = mx;
#pragma unroll
        for (int o = 16; o; o >>= 1) s += __shfl_xor_sync(0xffffffffu, s, o);
        if (lane == 0) logits[b * BB + a_idx] = s / (float)num_query[b];

        float se = 0.f;
#pragma unroll
        for (int v = 0; v < 64; v++) { float e = __expf(row[v] - mx); se += e; row[v] = e; }
        const float rinv = 1.0f / se;
#pragma unroll
        for (int v = 0; v < 64; v++) row[v] *= rinv;
    }
    __syncthreads();

    // att_obj_sum: warp w -> block w>>1, col half (w&1)
    {
        const int bk = wid >> 1;
        const int col = (wid & 1) * 32 + lane;
        float s = 0.f;
#pragma unroll
        for (int q = 0; q < 32; q++) s += sm.Cs[(bk * 32 + q) * 65 + col];
        const int b = (m0 >> 5) + bk;
        attsum[((size_t)b * BB + a_idx) * NKv + col] = s;
    }
}

// ---------------- launch ------------------------------------------------------
extern "C" void kernel_launch(void* const* d_in, const int* in_sizes, int n_in,
                              void* d_out, int out_size)
{
    const int*   query     = (const int*)  d_in[1];
    const int*   label     = (const int*)  d_in[2];
    const float* feature   = (const float*)d_in[3];
    const int*   num_query = (const int*)  d_in[7];
    const float* wv        = (const float*)d_in[8];
    const float* Wp        = (const float*)d_in[9];
    const float* bp        = (const float*)d_in[10];
    const float* Wm        = (const float*)d_in[11];
    const float* bm        = (const float*)d_in[12];
    const float* Wf        = (const float*)d_in[13];
    const float* bf        = (const float*)d_in[14];

    float* out    = (float*)d_out;
    float* logits = out;
    float* target = out + BB * BB;
    float* attsum = out + 2 * BB * BB;

    float* d_Wc; cudaGetSymbolAddress((void**)&d_Wc, g_Wc);
    float* d_bc; cudaGetSymbolAddress((void**)&d_bc, g_bc);
    float* d_p0; cudaGetSymbolAddress((void**)&d_p0, g_p0);
    float* d_ke; cudaGetSymbolAddress((void**)&d_ke, g_kemb);
    float* d_pe; cudaGetSymbolAddress((void**)&d_pe, g_pembr);

    combine_kernel<<<(EMBv * EMBv + 255) / 256, 256>>>(Wp, bp, Wm, bm);

    // k_emb = rna( feature @ Wf^T + wv[label] + bf )   [M=8192, N=300, K=2048]
    mma_gemm_kernel<<<dim3(5, 64), 256>>>(feature, FEATv, FEATv / 4,
                                          Wf, FEATv, EMBv, FEATv / 4,
                                          FEATv / 32, 0, 1, 1,
                                          bf, wv, label, d_ke);

    p0_kernel<<<BB * NQv, 384>>>(query, wv);

    // p_emb = rna( p0 @ Wc^T + bc )   [M=4096, N=300, K=300]
    mma_gemm_kernel<<<dim3(5, 32), 256>>>(d_p0, EMBv, (EMBv + 3) / 4,
                                          d_Wc, EMBv, EMBv, (EMBv + 3) / 4,
                                          10, 1, 1, 0,
                                          d_bc, nullptr, nullptr, d_pe);

    // attmap + fused softmax/max/sum
    attmap_mma_kernel<<<dim3(BB, 32), 256>>>(logits, attsum, num_query);

    eye_kernel<<<(BB * BB + 255) / 256, 256>>>(target);
}

// round 4
// speedup vs baseline: 1.3410x; 1.2914x over previous
#include <cuda_runtime.h>
#include <math.h>
#include <stdint.h>

#define BB    128
#define NQv   32
#define NWv   12
#define NKv   64
#define EMBv  300
#define KP    320
#define FEATv 2048
#define EPSV  1e-5f

#define LDS_ROW 36            // 32 floats + 4 pad: bank = 4*row + k (bijective)
#define SBUF (128 * LDS_ROW)  // one operand buffer (floats)
#define SMEM_BYTES (4 * SBUF * 4)   // 2 buffers x (A + B) x 4B = 73728

// ---------------- scratch (device globals; zero-initialized) ------------------
__device__ float g_featr[BB * NKv * FEATv];   // rna-rounded feature (64MB)
__device__ float g_Wfr  [EMBv * FEATv];       // rna-rounded Wf
__device__ float g_kemb [BB * NKv * KP];      // rounded k_emb, cols 300..319 = 0
__device__ float g_p0   [BB * NQv * EMBv];    // rounded p0
__device__ float g_pembr[BB * NQv * KP];      // rounded p_emb, cols 300..319 = 0
__device__ float g_Wc   [EMBv * EMBv];        // rna(Wp + EPS*Wm)
__device__ float g_bc   [EMBv];

// ---------------- helpers -----------------------------------------------------
__device__ __forceinline__ float rna_tf32(float x) {
    uint32_t u; asm("cvt.rna.tf32.f32 %0, %1;" : "=r"(u) : "f"(x));
    return __uint_as_float(u);
}
__device__ __forceinline__ void mma_tf32(float* d, const float* a, const float* b) {
    asm volatile(
        "mma.sync.aligned.m16n8k8.row.col.f32.tf32.tf32.f32 "
        "{%0,%1,%2,%3}, {%4,%5,%6,%7}, {%8,%9}, {%0,%1,%2,%3};\n"
        : "+f"(d[0]), "+f"(d[1]), "+f"(d[2]), "+f"(d[3])
        : "r"(__float_as_uint(a[0])), "r"(__float_as_uint(a[1])),
          "r"(__float_as_uint(a[2])), "r"(__float_as_uint(a[3])),
          "r"(__float_as_uint(b[0])), "r"(__float_as_uint(b[1])));
}
__device__ __forceinline__ void cp16(uint32_t s, const void* g, int nbytes) {
    asm volatile("cp.async.cg.shared.global [%0], [%1], 16, %2;"
                 :: "r"(s), "l"(g), "r"(nbytes));
}
#define CP_COMMIT() asm volatile("cp.async.commit_group;" ::: "memory")
#define CP_WAIT1()  asm volatile("cp.async.wait_group 1;" ::: "memory")
#define CP_WAIT0()  asm volatile("cp.async.wait_group 0;" ::: "memory")

// stage one 128x32 chunk (A: rows m0.., guarded K; B: rows n0.., guarded rows+K)
__device__ __forceinline__ void stage_chunk(
    uint32_t sA, uint32_t sB, int t, int c,
    const float* __restrict__ A, int lda, int aK4, int m0,
    const float* __restrict__ B, int ldb, int bK4, int bRows, int n0)
{
#pragma unroll
    for (int it = 0; it < 4; it++) {
        int idx = it * 256 + t;
        int m = idx >> 3, p = idx & 7;
        int f4 = c * 8 + p;
        cp16(sA + (uint32_t)(m * LDS_ROW + p * 4) * 4,
             A + (size_t)(m0 + m) * lda + f4 * 4,
             (f4 < aK4) ? 16 : 0);
    }
#pragma unroll
    for (int it = 0; it < 4; it++) {
        int idx = it * 256 + t;
        int r = idx >> 3, p = idx & 7;
        int f4 = c * 8 + p;
        cp16(sB + (uint32_t)(r * LDS_ROW + p * 4) * 4,
             B + (size_t)(n0 + r) * ldb + f4 * 4,
             (f4 < bK4 && (n0 + r) < bRows) ? 16 : 0);
    }
}

// compute one 32-K chunk: warp tile 32x64, acc[2][8][4]
__device__ __forceinline__ void compute_chunk(
    const float* __restrict__ As, const float* __restrict__ Bs,
    int wm, int wn, int g, int tid4, float acc[2][8][4])
{
#pragma unroll
    for (int ks = 0; ks < 4; ks++) {
        const int kb = ks * 8;
        float a[2][4];
#pragma unroll
        for (int i = 0; i < 2; i++) {
            int row = wm * 32 + i * 16 + g;
            a[i][0] = As[row * LDS_ROW + kb + tid4];
            a[i][1] = As[(row + 8) * LDS_ROW + kb + tid4];
            a[i][2] = As[row * LDS_ROW + kb + tid4 + 4];
            a[i][3] = As[(row + 8) * LDS_ROW + kb + tid4 + 4];
        }
        float b[8][2];
#pragma unroll
        for (int j = 0; j < 8; j++) {
            int col = wn * 64 + j * 8 + g;
            b[j][0] = Bs[col * LDS_ROW + kb + tid4];
            b[j][1] = Bs[col * LDS_ROW + kb + tid4 + 4];
        }
#pragma unroll
        for (int i = 0; i < 2; i++)
#pragma unroll
            for (int j = 0; j < 8; j++) mma_tf32(acc[i][j], a[i], b[j]);
    }
}

// ---------------- small kernels ------------------------------------------------
__global__ void round_feat_kernel(const float* __restrict__ f)
{
    int i = blockIdx.x * blockDim.x + threadIdx.x;
    float4 v = ((const float4*)f)[i];
    v.x = rna_tf32(v.x); v.y = rna_tf32(v.y); v.z = rna_tf32(v.z); v.w = rna_tf32(v.w);
    ((float4*)g_featr)[i] = v;
}
__global__ void round_wf_kernel(const float* __restrict__ Wf)
{
    int i = blockIdx.x * blockDim.x + threadIdx.x;
    if (i < EMBv * FEATv / 4) {
        float4 v = ((const float4*)Wf)[i];
        v.x = rna_tf32(v.x); v.y = rna_tf32(v.y); v.z = rna_tf32(v.z); v.w = rna_tf32(v.w);
        ((float4*)g_Wfr)[i] = v;
    }
}
__global__ void combine_kernel(const float* __restrict__ Wp, const float* __restrict__ bp,
                               const float* __restrict__ Wm, const float* __restrict__ bm)
{
    int i = blockIdx.x * blockDim.x + threadIdx.x;
    if (i < EMBv * EMBv) g_Wc[i] = rna_tf32(Wp[i] + EPSV * Wm[i]);
    if (i < EMBv)        g_bc[i] = bp[i] + EPSV * bm[i];
}
__global__ void eye_kernel(float* __restrict__ target)
{
    int i = blockIdx.x * blockDim.x + threadIdx.x;
    if (i < BB * BB) target[i] = ((i / BB) == (i % BB)) ? 1.0f : 0.0f;
}

// ---------------- generic pipelined tf32 GEMM: out = rna(A*B^T + epi) ---------
// Block tile 128x128, 256 threads, warps 4(m) x 2(n), warp tile 32x64.
__global__ __launch_bounds__(256, 2) void mma_gemm_async(
    const float* __restrict__ A, int lda, int aK4,
    const float* __restrict__ B, int ldb, int bRows, int bK4,
    int nChunks, int mode, const float* __restrict__ bias,
    const float* __restrict__ wv, const int* __restrict__ label,
    float* __restrict__ out)
{
    extern __shared__ float smem[];
    const int m0 = blockIdx.y * 128;
    const int n0 = blockIdx.x * 128;
    const int t  = threadIdx.x;
    const int wid = t >> 5, lane = t & 31;
    const int wm = wid & 3, wn = wid >> 2;
    const int g = lane >> 2, tid4 = lane & 3;

    uint32_t sb = (uint32_t)__cvta_generic_to_shared(smem);

    float acc[2][8][4];
#pragma unroll
    for (int i = 0; i < 2; i++)
#pragma unroll
        for (int j = 0; j < 8; j++)
#pragma unroll
            for (int r = 0; r < 4; r++) acc[i][j][r] = 0.0f;

    // prologue: chunk 0 -> buffer 0
    stage_chunk(sb, sb + SBUF * 4, t, 0, A, lda, aK4, m0, B, ldb, bK4, bRows, n0);
    CP_COMMIT();

    for (int c = 0; c < nChunks; c++) {
        if (c + 1 < nChunks) {
            uint32_t boff = ((c + 1) & 1) ? 2u * SBUF * 4u : 0u;
            stage_chunk(sb + boff, sb + boff + SBUF * 4, t, c + 1,
                        A, lda, aK4, m0, B, ldb, bK4, bRows, n0);
            CP_COMMIT();
            CP_WAIT1();
        } else {
            CP_WAIT0();
        }
        __syncthreads();
        const float* As = smem + ((c & 1) ? 2 * SBUF : 0);
        const float* Bs = As + SBUF;
        compute_chunk(As, Bs, wm, wn, g, tid4, acc);
        __syncthreads();
    }

    // epilogue: rounded store, stride KP, cols < EMBv
#pragma unroll
    for (int i = 0; i < 2; i++) {
#pragma unroll
        for (int rh = 0; rh < 2; rh++) {
            int gm = m0 + wm * 32 + i * 16 + g + rh * 8;
            const float* wrow = (mode == 0) ? (wv + (size_t)label[gm] * EMBv) : nullptr;
#pragma unroll
            for (int j = 0; j < 8; j++) {
#pragma unroll
                for (int q = 0; q < 2; q++) {
                    int gn = n0 + wn * 64 + j * 8 + 2 * tid4 + q;
                    if (gn < EMBv) {
                        float v = acc[i][j][rh * 2 + q] + bias[gn];
                        if (mode == 0) v += wrow[gn];
                        out[(size_t)gm * KP + gn] = rna_tf32(v);
                    }
                }
            }
        }
    }
}

// ---------------- attmap: same mainloop + fused softmax/max/sum ---------------
#define CS_LD 129
__global__ __launch_bounds__(256, 2) void attmap_mma_async(
    float* __restrict__ logits, float* __restrict__ attsum,
    const int* __restrict__ num_query)
{
    extern __shared__ float smem[];
    const int m0 = blockIdx.y * 128;   // pemb rows (4 b-blocks)
    const int n0 = blockIdx.x * 128;   // kemb rows (2 a-blocks)
    const int t  = threadIdx.x;
    const int wid = t >> 5, lane = t & 31;
    const int wm = wid & 3, wn = wid >> 2;
    const int g = lane >> 2, tid4 = lane & 3;

    uint32_t sb = (uint32_t)__cvta_generic_to_shared(smem);

    float acc[2][8][4];
#pragma unroll
    for (int i = 0; i < 2; i++)
#pragma unroll
        for (int j = 0; j < 8; j++)
#pragma unroll
            for (int r = 0; r < 4; r++) acc[i][j][r] = 0.0f;

    stage_chunk(sb, sb + SBUF * 4, t, 0, g_pembr, KP, KP / 4, m0,
                g_kemb, KP, KP / 4, BB * NKv, n0);
    CP_COMMIT();

    const int NCH = KP / 32;
    for (int c = 0; c < NCH; c++) {
        if (c + 1 < NCH) {
            uint32_t boff = ((c + 1) & 1) ? 2u * SBUF * 4u : 0u;
            stage_chunk(sb + boff, sb + boff + SBUF * 4, t, c + 1,
                        g_pembr, KP, KP / 4, m0, g_kemb, KP, KP / 4, BB * NKv, n0);
            CP_COMMIT();
            CP_WAIT1();
        } else {
            CP_WAIT0();
        }
        __syncthreads();
        const float* As = smem + ((c & 1) ? 2 * SBUF : 0);
        const float* Bs = As + SBUF;
        compute_chunk(As, Bs, wm, wn, g, tid4, acc);
        __syncthreads();
    }

    // C tile -> smem [128][CS_LD] (reuse pipeline buffers)
    float* Cs = smem;
#pragma unroll
    for (int i = 0; i < 2; i++) {
#pragma unroll
        for (int rh = 0; rh < 2; rh++) {
            int row = wm * 32 + i * 16 + g + rh * 8;
#pragma unroll
            for (int j = 0; j < 8; j++) {
                int col = wn * 64 + j * 8 + 2 * tid4;
                Cs[row * CS_LD + col]     = acc[i][j][rh * 2 + 0];
                Cs[row * CS_LD + col + 1] = acc[i][j][rh * 2 + 1];
            }
        }
    }
    __syncthreads();

    // warp -> (b,a) sub-block of 32 q-rows x 64 v-cols
    const int bk = wid & 3, ah = wid >> 2;
    const int b = (m0 >> 5) + bk;
    const int a = (n0 >> 6) + ah;
    float* row = &Cs[(bk * 32 + lane) * CS_LD + ah * 64];

    float mx = -1e30f;
#pragma unroll
    for (int v = 0; v < 64; v++) mx = fmaxf(mx, row[v]);

    float s = mx;
#pragma unroll
    for (int o = 16; o; o >>= 1) s += __shfl_xor_sync(0xffffffffu, s, o);
    if (lane == 0) logits[b * BB + a] = s / (float)num_query[b];

    float se = 0.f;
#pragma unroll
    for (int v = 0; v < 64; v++) { float e = __expf(row[v] - mx); se += e; row[v] = e; }
    const float rinv = 1.0f / se;
#pragma unroll
    for (int v = 0; v < 64; v++) row[v] *= rinv;
    __syncthreads();

    // att_obj_sum over q within the same sub-block
    {
        float s0 = 0.f, s1 = 0.f;
        const float* base = &Cs[(bk * 32) * CS_LD + ah * 64];
#pragma unroll
        for (int q = 0; q < 32; q++) {
            s0 += base[q * CS_LD + lane];
            s1 += base[q * CS_LD + lane + 32];
        }
        attsum[((size_t)b * BB + a) * NKv + lane]      = s0;
        attsum[((size_t)b * BB + a) * NKv + lane + 32] = s1;
    }
}

// ---------------- per-(b,q): word attention -> p0 (scalar) --------------------
__global__ __launch_bounds__(384) void p0_kernel(const int* __restrict__ query,
                                                 const float* __restrict__ wv)
{
    __shared__ float Qs[NWv][304];
    __shared__ int   qi[NWv];
    __shared__ float qma[NWv];
    __shared__ float qnorm[NWv];

    const int b  = blockIdx.x >> 5;
    const int qy = blockIdx.x & 31;
    const int t  = threadIdx.x;
    const int warp = t >> 5, lane = t & 31;

    if (t < NWv) qi[t] = query[(b * NQv + qy) * NWv + t];
    __syncthreads();
#pragma unroll
    for (int p = 0; p < 3; p++) {
        int idx = p * 384 + t;
        if (idx < 900) {
            int r = idx / 75, c = idx % 75;
            *(float4*)&Qs[r][c * 4] = *(const float4*)(wv + (size_t)qi[r] * EMBv + c * 4);
        }
    }
    __syncthreads();

    const float* k0p = g_kemb + (size_t)(b * NKv + lane) * KP;
    const float* k1p = g_kemb + (size_t)(b * NKv + lane + 32) * KP;
    float acc0 = 0.f, acc1 = 0.f;
#pragma unroll 5
    for (int d4 = 0; d4 < 75; d4++) {
        float4 q4 = *(const float4*)&Qs[warp][d4 * 4];
        float4 a4 = *(const float4*)(k0p + d4 * 4);
        float4 c4 = *(const float4*)(k1p + d4 * 4);
        acc0 += q4.x * a4.x + q4.y * a4.y + q4.z * a4.z + q4.w * a4.w;
        acc1 += q4.x * c4.x + q4.y * c4.y + q4.z * c4.z + q4.w * c4.w;
    }
    const float scale = rsqrtf((float)EMBv);
    acc0 *= scale; acc1 *= scale;

    float mx = fmaxf(acc0, acc1);
#pragma unroll
    for (int o = 16; o; o >>= 1) mx = fmaxf(mx, __shfl_xor_sync(0xffffffffu, mx, o));
    float se = __expf(acc0 - mx) + __expf(acc1 - mx);
#pragma unroll
    for (int o = 16; o; o >>= 1) se += __shfl_xor_sync(0xffffffffu, se, o);
    if (lane == 0) qma[warp] = 1.0f / se;
    __syncthreads();

    if (warp == 0) {
        float v = (lane < NWv) ? qma[lane] : -1e30f;
        float m2 = v;
#pragma unroll
        for (int o = 16; o; o >>= 1) m2 = fmaxf(m2, __shfl_xor_sync(0xffffffffu, m2, o));
        float e = (lane < NWv) ? __expf(v - m2) : 0.f;
        float s2 = e;
#pragma unroll
        for (int o = 16; o; o >>= 1) s2 += __shfl_xor_sync(0xffffffffu, s2, o);
        if (lane < NWv) qnorm[lane] = e / s2;
    }
    __syncthreads();

    if (t < EMBv) {
        float s = 0.f;
#pragma unroll
        for (int w = 0; w < NWv; w++) s += qnorm[w] * Qs[w][t];
        g_p0[(size_t)(b * NQv + qy) * EMBv + t] = rna_tf32(s);
    }
}

// ---------------- launch ------------------------------------------------------
extern "C" void kernel_launch(void* const* d_in, const int* in_sizes, int n_in,
                              void* d_out, int out_size)
{
    const int*   query     = (const int*)  d_in[1];
    const int*   label     = (const int*)  d_in[2];
    const float* feature   = (const float*)d_in[3];
    const int*   num_query = (const int*)  d_in[7];
    const float* wv        = (const float*)d_in[8];
    const float* Wp        = (const float*)d_in[9];
    const float* bp        = (const float*)d_in[10];
    const float* Wm        = (const float*)d_in[11];
    const float* bm        = (const float*)d_in[12];
    const float* Wf        = (const float*)d_in[13];
    const float* bf        = (const float*)d_in[14];

    float* out    = (float*)d_out;
    float* logits = out;
    float* target = out + BB * BB;
    float* attsum = out + 2 * BB * BB;

    static int smem_set = 0;
    if (!smem_set) {
        cudaFuncSetAttribute(mma_gemm_async,
                             cudaFuncAttributeMaxDynamicSharedMemorySize, SMEM_BYTES);
        cudaFuncSetAttribute(attmap_mma_async,
                             cudaFuncAttributeMaxDynamicSharedMemorySize, SMEM_BYTES);
        smem_set = 1;
    }

    float* d_featr; cudaGetSymbolAddress((void**)&d_featr, g_featr);
    float* d_Wfr;   cudaGetSymbolAddress((void**)&d_Wfr,   g_Wfr);
    float* d_Wc;    cudaGetSymbolAddress((void**)&d_Wc,    g_Wc);
    float* d_bc;    cudaGetSymbolAddress((void**)&d_bc,    g_bc);
    float* d_p0;    cudaGetSymbolAddress((void**)&d_p0,    g_p0);
    float* d_ke;    cudaGetSymbolAddress((void**)&d_ke,    g_kemb);
    float* d_pe;    cudaGetSymbolAddress((void**)&d_pe,    g_pembr);

    round_feat_kernel<<<(BB * NKv * FEATv / 4) / 256, 256>>>(feature);
    round_wf_kernel<<<(EMBv * FEATv / 4 + 255) / 256, 256>>>(Wf);
    combine_kernel<<<(EMBv * EMBv + 255) / 256, 256>>>(Wp, bp, Wm, bm);

    // k_emb = rna( feature @ Wf^T + wv[label] + bf )  [8192 x 300 x 2048]
    mma_gemm_async<<<dim3(3, 64), 256, SMEM_BYTES>>>(
        d_featr, FEATv, FEATv / 4, d_Wfr, FEATv, EMBv, FEATv / 4,
        FEATv / 32, 0, bf, wv, label, d_ke);

    p0_kernel<<<BB * NQv, 384>>>(query, wv);

    // p_emb = rna( p0 @ Wc^T + bc )  [4096 x 300 x 300]
    mma_gemm_async<<<dim3(3, 32), 256, SMEM_BYTES>>>(
        d_p0, EMBv, 75, d_Wc, EMBv, EMBv, 75,
        10, 1, d_bc, nullptr, nullptr, d_pe);

    // attmap + fused softmax/max/sum  [4096 x 8192 x 320]
    attmap_mma_async<<<dim3(64, 32), 256, SMEM_BYTES>>>(logits, attsum, num_query);

    eye_kernel<<<(BB * BB + 255) / 256, 256>>>(target);
}

// round 5
// speedup vs baseline: 2.9351x; 2.1887x over previous
#include <cuda_runtime.h>
#include <math.h>
#include <stdint.h>

#define BB    128
#define NQv   32
#define NWv   12
#define NKv   64
#define EMBv  300
#define KP    320
#define FEATv 2048
#define EPSV  1e-5f

#define LDS_ROW 36                 // 32 floats + 4 pad
#define SBUF (128 * LDS_ROW)       // floats per operand per stage
#define NSTAGE 3
#define STAGE_F (2 * SBUF)         // A + B per stage
#define SMEM_BYTES (NSTAGE * STAGE_F * 4)   // 110592 B

// ---------------- scratch (device globals; zero-initialized) ------------------
__device__ float g_Wfr  [EMBv * FEATv];       // rna-rounded Wf
__device__ float g_kemb [BB * NKv * KP];      // rounded k_emb, cols 300..319 = 0
__device__ float g_p0   [BB * NQv * EMBv];    // rounded p0
__device__ float g_pembr[BB * NQv * KP];      // rounded p_emb, cols 300..319 = 0
__device__ float g_Wc   [EMBv * EMBv];        // rna(Wp + EPS*Wm)
__device__ float g_bc   [EMBv];

// ---------------- helpers -----------------------------------------------------
__device__ __forceinline__ float rna_tf32(float x) {
    uint32_t u; asm("cvt.rna.tf32.f32 %0, %1;" : "=r"(u) : "f"(x));
    return __uint_as_float(u);
}
__device__ __forceinline__ void mma_tf32(float* d, const float* a, const float* b) {
    asm volatile(
        "mma.sync.aligned.m16n8k8.row.col.f32.tf32.tf32.f32 "
        "{%0,%1,%2,%3}, {%4,%5,%6,%7}, {%8,%9}, {%0,%1,%2,%3};\n"
        : "+f"(d[0]), "+f"(d[1]), "+f"(d[2]), "+f"(d[3])
        : "r"(__float_as_uint(a[0])), "r"(__float_as_uint(a[1])),
          "r"(__float_as_uint(a[2])), "r"(__float_as_uint(a[3])),
          "r"(__float_as_uint(b[0])), "r"(__float_as_uint(b[1])));
}
__device__ __forceinline__ void cp16(uint32_t s, const void* g, int nbytes) {
    asm volatile("cp.async.cg.shared.global [%0], [%1], 16, %2;"
                 :: "r"(s), "l"(g), "r"(nbytes));
}
#define CP_COMMIT() asm volatile("cp.async.commit_group;" ::: "memory")
#define CP_WAIT1()  asm volatile("cp.async.wait_group 1;" ::: "memory")
#define CP_WAIT0()  asm volatile("cp.async.wait_group 0;" ::: "memory")

__device__ __forceinline__ void stage_chunk(
    uint32_t base, int t, int c,
    const float* __restrict__ A, int lda, int aK4, int m0,
    const float* __restrict__ B, int ldb, int bK4, int bRows, int n0)
{
    uint32_t sA = base, sB = base + SBUF * 4;
#pragma unroll
    for (int it = 0; it < 4; it++) {
        int idx = it * 256 + t;
        int m = idx >> 3, p = idx & 7;
        int f4 = c * 8 + p;
        cp16(sA + (uint32_t)(m * LDS_ROW + p * 4) * 4,
             A + (size_t)(m0 + m) * lda + f4 * 4, (f4 < aK4) ? 16 : 0);
    }
#pragma unroll
    for (int it = 0; it < 4; it++) {
        int idx = it * 256 + t;
        int r = idx >> 3, p = idx & 7;
        int f4 = c * 8 + p;
        cp16(sB + (uint32_t)(r * LDS_ROW + p * 4) * 4,
             B + (size_t)(n0 + r) * ldb + f4 * 4,
             (f4 < bK4 && (n0 + r) < bRows) ? 16 : 0);
    }
}

__device__ __forceinline__ void compute_chunk(
    const float* __restrict__ As, const float* __restrict__ Bs,
    int wm, int wn, int g, int tid4, float acc[2][8][4])
{
#pragma unroll
    for (int ks = 0; ks < 4; ks++) {
        const int kb = ks * 8;
        float a[2][4];
#pragma unroll
        for (int i = 0; i < 2; i++) {
            int row = wm * 32 + i * 16 + g;
            a[i][0] = As[row * LDS_ROW + kb + tid4];
            a[i][1] = As[(row + 8) * LDS_ROW + kb + tid4];
            a[i][2] = As[row * LDS_ROW + kb + tid4 + 4];
            a[i][3] = As[(row + 8) * LDS_ROW + kb + tid4 + 4];
        }
        float b[8][2];
#pragma unroll
        for (int j = 0; j < 8; j++) {
            int col = wn * 64 + j * 8 + g;
            b[j][0] = Bs[col * LDS_ROW + kb + tid4];
            b[j][1] = Bs[col * LDS_ROW + kb + tid4 + 4];
        }
#pragma unroll
        for (int i = 0; i < 2; i++)
#pragma unroll
            for (int j = 0; j < 8; j++) mma_tf32(acc[i][j], a[i], b[j]);
    }
}

// ---------------- small kernels ------------------------------------------------
__global__ void round_wf_kernel(const float* __restrict__ Wf)
{
    int i = blockIdx.x * blockDim.x + threadIdx.x;
    if (i < EMBv * FEATv / 4) {
        float4 v = ((const float4*)Wf)[i];
        v.x = rna_tf32(v.x); v.y = rna_tf32(v.y); v.z = rna_tf32(v.z); v.w = rna_tf32(v.w);
        ((float4*)g_Wfr)[i] = v;
    }
}
__global__ void combine_kernel(const float* __restrict__ Wp, const float* __restrict__ bp,
                               const float* __restrict__ Wm, const float* __restrict__ bm)
{
    int i = blockIdx.x * blockDim.x + threadIdx.x;
    if (i < EMBv * EMBv) g_Wc[i] = rna_tf32(Wp[i] + EPSV * Wm[i]);
    if (i < EMBv)        g_bc[i] = bp[i] + EPSV * bm[i];
}
__global__ void eye_kernel(float* __restrict__ target)
{
    int i = blockIdx.x * blockDim.x + threadIdx.x;
    if (i < BB * BB) target[i] = ((i / BB) == (i % BB)) ? 1.0f : 0.0f;
}

// ---------------- pipelined tf32 GEMM: out = rna(A*B^T + epi), 3 stages -------
__global__ __launch_bounds__(256, 2) void mma_gemm_async(
    const float* __restrict__ A, int lda, int aK4,
    const float* __restrict__ B, int ldb, int bRows, int bK4,
    int nChunks, int mode, const float* __restrict__ bias,
    const float* __restrict__ wv, const int* __restrict__ label,
    float* __restrict__ out)
{
    extern __shared__ float smem[];
    const int m0 = blockIdx.y * 128;
    const int n0 = blockIdx.x * 128;
    const int t  = threadIdx.x;
    const int wid = t >> 5, lane = t & 31;
    const int wm = wid & 3, wn = wid >> 2;
    const int g = lane >> 2, tid4 = lane & 3;

    uint32_t sb = (uint32_t)__cvta_generic_to_shared(smem);

    float acc[2][8][4];
#pragma unroll
    for (int i = 0; i < 2; i++)
#pragma unroll
        for (int j = 0; j < 8; j++)
#pragma unroll
            for (int r = 0; r < 4; r++) acc[i][j][r] = 0.0f;

    stage_chunk(sb, t, 0, A, lda, aK4, m0, B, ldb, bK4, bRows, n0);
    CP_COMMIT();
    stage_chunk(sb + STAGE_F * 4, t, 1, A, lda, aK4, m0, B, ldb, bK4, bRows, n0);
    CP_COMMIT();

    for (int c = 0; c < nChunks; c++) {
        if (c + 2 < nChunks) { CP_WAIT1(); } else { CP_WAIT0(); }
        __syncthreads();
        const float* As = smem + (c % 3) * STAGE_F;
        compute_chunk(As, As + SBUF, wm, wn, g, tid4, acc);
        if (c + 2 < nChunks) {
            stage_chunk(sb + ((c + 2) % 3) * STAGE_F * 4, t, c + 2,
                        A, lda, aK4, m0, B, ldb, bK4, bRows, n0);
            CP_COMMIT();
        }
    }

#pragma unroll
    for (int i = 0; i < 2; i++) {
#pragma unroll
        for (int rh = 0; rh < 2; rh++) {
            int gm = m0 + wm * 32 + i * 16 + g + rh * 8;
            const float* wrow = (mode == 0) ? (wv + (size_t)label[gm] * EMBv) : nullptr;
#pragma unroll
            for (int j = 0; j < 8; j++) {
#pragma unroll
                for (int q = 0; q < 2; q++) {
                    int gn = n0 + wn * 64 + j * 8 + 2 * tid4 + q;
                    if (gn < EMBv) {
                        float v = acc[i][j][rh * 2 + q] + bias[gn];
                        if (mode == 0) v += wrow[gn];
                        out[(size_t)gm * KP + gn] = rna_tf32(v);
                    }
                }
            }
        }
    }
}

// ---------------- attmap: pipelined MMA + fused softmax/max/sum ---------------
#define CS_LD 129
__global__ __launch_bounds__(256, 2) void attmap_mma_async(
    float* __restrict__ logits, float* __restrict__ attsum,
    const int* __restrict__ num_query)
{
    extern __shared__ float smem[];
    const int m0 = blockIdx.y * 128;
    const int n0 = blockIdx.x * 128;
    const int t  = threadIdx.x;
    const int wid = t >> 5, lane = t & 31;
    const int wm = wid & 3, wn = wid >> 2;
    const int g = lane >> 2, tid4 = lane & 3;

    uint32_t sb = (uint32_t)__cvta_generic_to_shared(smem);

    float acc[2][8][4];
#pragma unroll
    for (int i = 0; i < 2; i++)
#pragma unroll
        for (int j = 0; j < 8; j++)
#pragma unroll
            for (int r = 0; r < 4; r++) acc[i][j][r] = 0.0f;

    const int NCH = KP / 32;
    stage_chunk(sb, t, 0, g_pembr, KP, KP / 4, m0, g_kemb, KP, KP / 4, BB * NKv, n0);
    CP_COMMIT();
    stage_chunk(sb + STAGE_F * 4, t, 1, g_pembr, KP, KP / 4, m0,
                g_kemb, KP, KP / 4, BB * NKv, n0);
    CP_COMMIT();

    for (int c = 0; c < NCH; c++) {
        if (c + 2 < NCH) { CP_WAIT1(); } else { CP_WAIT0(); }
        __syncthreads();
        const float* As = smem + (c % 3) * STAGE_F;
        compute_chunk(As, As + SBUF, wm, wn, g, tid4, acc);
        if (c + 2 < NCH) {
            stage_chunk(sb + ((c + 2) % 3) * STAGE_F * 4, t, c + 2,
                        g_pembr, KP, KP / 4, m0, g_kemb, KP, KP / 4, BB * NKv, n0);
            CP_COMMIT();
        }
    }
    __syncthreads();    // all compute done before reusing smem as C tile

    float* Cs = smem;
#pragma unroll
    for (int i = 0; i < 2; i++) {
#pragma unroll
        for (int rh = 0; rh < 2; rh++) {
            int row = wm * 32 + i * 16 + g + rh * 8;
#pragma unroll
            for (int j = 0; j < 8; j++) {
                int col = wn * 64 + j * 8 + 2 * tid4;
                Cs[row * CS_LD + col]     = acc[i][j][rh * 2 + 0];
                Cs[row * CS_LD + col + 1] = acc[i][j][rh * 2 + 1];
            }
        }
    }
    __syncthreads();

    const int bk = wid & 3, ah = wid >> 2;
    const int b = (m0 >> 5) + bk;
    const int a = (n0 >> 6) + ah;
    float* row = &Cs[(bk * 32 + lane) * CS_LD + ah * 64];

    float mx = -1e30f;
#pragma unroll
    for (int v = 0; v < 64; v++) mx = fmaxf(mx, row[v]);

    float s = mx;
#pragma unroll
    for (int o = 16; o; o >>= 1) s += __shfl_xor_sync(0xffffffffu, s, o);
    if (lane == 0) logits[b * BB + a] = s / (float)num_query[b];

    float se = 0.f;
#pragma unroll
    for (int v = 0; v < 64; v++) { float e = __expf(row[v] - mx); se += e; row[v] = e; }
    const float rinv = 1.0f / se;
#pragma unroll
    for (int v = 0; v < 64; v++) row[v] *= rinv;
    __syncthreads();

    {
        float s0 = 0.f, s1 = 0.f;
        const float* base = &Cs[(bk * 32) * CS_LD + ah * 64];
#pragma unroll
        for (int q = 0; q < 32; q++) {
            s0 += base[q * CS_LD + lane];
            s1 += base[q * CS_LD + lane + 32];
        }
        attsum[((size_t)b * BB + a) * NKv + lane]      = s0;
        attsum[((size_t)b * BB + a) * NKv + lane + 32] = s1;
    }
}

// ---------------- p0: K tile in smem, thread=k mapping ------------------------
#define KS_LD 308
#define QS_LD 304
#define P0_SMEM_F (64 * KS_LD + 12 * QS_LD + 64 * 13 + 24 + 24 + 12 + 12 + 12)
#define P0_SMEM_BYTES (P0_SMEM_F * 4)

__global__ __launch_bounds__(128, 2) void p0_kernel(const int* __restrict__ query,
                                                    const float* __restrict__ wv)
{
    extern __shared__ float ps[];
    float* Ks    = ps;                     // [64][KS_LD]
    float* Qs    = Ks + 64 * KS_LD;        // [12][QS_LD]
    float* pacc  = Qs + 12 * QS_LD;        // [64][13]
    float* wmx   = pacc + 64 * 13;         // [2][12]
    float* wse   = wmx + 24;               // [2][12]
    float* qma   = wse + 24;               // [12]
    float* qnorm = qma + 12;               // [12]
    int*   qi    = (int*)(qnorm + 12);     // [12]

    const int b  = blockIdx.x >> 5;
    const int qy = blockIdx.x & 31;
    const int t  = threadIdx.x;
    const int warp = t >> 5, lane = t & 31;

    if (t < NWv) qi[t] = query[(b * NQv + qy) * NWv + t];
    __syncthreads();

    // stage K tile coalescedly: 64 rows x 75 float4
    const float* kb = g_kemb + (size_t)b * NKv * KP;
    for (int idx = t; idx < 64 * 75; idx += 128) {
        int r = idx / 75, c = idx % 75;
        *(float4*)&Ks[r * KS_LD + c * 4] = *(const float4*)(kb + (size_t)r * KP + c * 4);
    }
    // gather Q rows
    for (int idx = t; idx < 12 * 75; idx += 128) {
        int r = idx / 75, c = idx % 75;
        *(float4*)&Qs[r * QS_LD + c * 4] = *(const float4*)(wv + (size_t)qi[r] * EMBv + c * 4);
    }
    __syncthreads();

    // thread (k = t&63, dh = t>>6): 12 word-dots over a d-half
    const int k = t & 63, dh = t >> 6;
    const int d0 = dh ? 38 : 0, d1 = dh ? 75 : 38;
    float acc[12];
#pragma unroll
    for (int w = 0; w < 12; w++) acc[w] = 0.f;
    const float* krow = &Ks[k * KS_LD];
    for (int d4 = d0; d4 < d1; d4++) {
        float4 kv = *(const float4*)&krow[d4 * 4];
#pragma unroll
        for (int w = 0; w < 12; w++) {
            float4 q = *(const float4*)&Qs[w * QS_LD + d4 * 4];
            acc[w] += q.x * kv.x + q.y * kv.y + q.z * kv.z + q.w * kv.w;
        }
    }
    if (dh == 1) {
#pragma unroll
        for (int w = 0; w < 12; w++) pacc[k * 13 + w] = acc[w];
    }
    __syncthreads();

    if (dh == 0) {
        const float scale = rsqrtf((float)EMBv);
#pragma unroll
        for (int w = 0; w < 12; w++) {
            acc[w] = (acc[w] + pacc[k * 13 + w]) * scale;
            float m = acc[w];
#pragma unroll
            for (int o = 16; o; o >>= 1) m = fmaxf(m, __shfl_xor_sync(0xffffffffu, m, o));
            if (lane == 0) wmx[warp * 12 + w] = m;
        }
    }
    __syncthreads();
    if (dh == 0) {
#pragma unroll
        for (int w = 0; w < 12; w++) {
            float gm = fmaxf(wmx[w], wmx[12 + w]);
            float e = __expf(acc[w] - gm);
#pragma unroll
            for (int o = 16; o; o >>= 1) e += __shfl_xor_sync(0xffffffffu, e, o);
            if (lane == 0) wse[warp * 12 + w] = e;
        }
    }
    __syncthreads();
    if (warp == 0 && lane < 12) qma[lane] = 1.0f / (wse[lane] + wse[12 + lane]);
    __syncthreads();

    // softmax over the 12 words (warp 0)
    if (warp == 0) {
        float v = (lane < NWv) ? qma[lane] : -1e30f;
        float m2 = v;
#pragma unroll
        for (int o = 16; o; o >>= 1) m2 = fmaxf(m2, __shfl_xor_sync(0xffffffffu, m2, o));
        float e = (lane < NWv) ? __expf(v - m2) : 0.f;
        float s2 = e;
#pragma unroll
        for (int o = 16; o; o >>= 1) s2 += __shfl_xor_sync(0xffffffffu, s2, o);
        if (lane < NWv) qnorm[lane] = e / s2;
    }
    __syncthreads();

    for (int d = t; d < EMBv; d += 128) {
        float s = 0.f;
#pragma unroll
        for (int w = 0; w < 12; w++) s += qnorm[w] * Qs[w * QS_LD + d];
        g_p0[(size_t)(b * NQv + qy) * EMBv + d] = rna_tf32(s);
    }
}

// ---------------- launch ------------------------------------------------------
extern "C" void kernel_launch(void* const* d_in, const int* in_sizes, int n_in,
                              void* d_out, int out_size)
{
    const int*   query     = (const int*)  d_in[1];
    const int*   label     = (const int*)  d_in[2];
    const float* feature   = (const float*)d_in[3];
    const int*   num_query = (const int*)  d_in[7];
    const float* wv        = (const float*)d_in[8];
    const float* Wp        = (const float*)d_in[9];
    const float* bp        = (const float*)d_in[10];
    const float* Wm        = (const float*)d_in[11];
    const float* bm        = (const float*)d_in[12];
    const float* Wf        = (const float*)d_in[13];
    const float* bf        = (const float*)d_in[14];

    float* out    = (float*)d_out;
    float* logits = out;
    float* target = out + BB * BB;
    float* attsum = out + 2 * BB * BB;

    static int smem_set = 0;
    if (!smem_set) {
        cudaFuncSetAttribute(mma_gemm_async,
                             cudaFuncAttributeMaxDynamicSharedMemorySize, SMEM_BYTES);
        cudaFuncSetAttribute(attmap_mma_async,
                             cudaFuncAttributeMaxDynamicSharedMemorySize, SMEM_BYTES);
        cudaFuncSetAttribute(p0_kernel,
                             cudaFuncAttributeMaxDynamicSharedMemorySize, P0_SMEM_BYTES);
        smem_set = 1;
    }

    float* d_Wfr; cudaGetSymbolAddress((void**)&d_Wfr, g_Wfr);
    float* d_Wc;  cudaGetSymbolAddress((void**)&d_Wc,  g_Wc);
    float* d_bc;  cudaGetSymbolAddress((void**)&d_bc,  g_bc);
    float* d_p0;  cudaGetSymbolAddress((void**)&d_p0,  g_p0);
    float* d_ke;  cudaGetSymbolAddress((void**)&d_ke,  g_kemb);
    float* d_pe;  cudaGetSymbolAddress((void**)&d_pe,  g_pembr);

    round_wf_kernel<<<(EMBv * FEATv / 4 + 255) / 256, 256>>>(Wf);
    combine_kernel<<<(EMBv * EMBv + 255) / 256, 256>>>(Wp, bp, Wm, bm);

    // k_emb = rna( feature @ Wf^T + wv[label] + bf )  [8192 x 300 x 2048]
    mma_gemm_async<<<dim3(3, 64), 256, SMEM_BYTES>>>(
        feature, FEATv, FEATv / 4, d_Wfr, FEATv, EMBv, FEATv / 4,
        FEATv / 32, 0, bf, wv, label, d_ke);

    p0_kernel<<<BB * NQv, 128, P0_SMEM_BYTES>>>(query, wv);

    // p_emb = rna( p0 @ Wc^T + bc )  [4096 x 300 x 300]
    mma_gemm_async<<<dim3(3, 32), 256, SMEM_BYTES>>>(
        d_p0, EMBv, 75, d_Wc, EMBv, EMBv, 75,
        10, 1, d_bc, nullptr, nullptr, d_pe);

    // attmap + fused softmax/max/sum  [4096 x 8192 x 320]
    attmap_mma_async<<<dim3(64, 32), 256, SMEM_BYTES>>>(logits, attsum, num_query);

    eye_kernel<<<(BB * BB + 255) / 256, 256>>>(target);
}

// round 6
// speedup vs baseline: 4.5726x; 1.5579x over previous
#include <cuda_runtime.h>
#include <math.h>
#include <stdint.h>

#define BB    128
#define NQv   32
#define NWv   12
#define NKv   64
#define EMBv  300
#define KP    320
#define FEATv 2048
#define EPSV  1e-5f

#define LDS_ROW 36                 // 32 floats + 4 pad
#define SBUF (128 * LDS_ROW)
#define NSTAGE 3
#define STAGE_F (2 * SBUF)
#define SMEM_BYTES (NSTAGE * STAGE_F * 4)

// ---------------- scratch (device globals; zero-initialized) ------------------
__device__ float g_Wfr  [EMBv * FEATv];
__device__ float g_kemb [BB * NKv * KP];      // cols 300..319 stay zero
__device__ float g_p0   [BB * NQv * EMBv];
__device__ float g_pembr[BB * NQv * KP];      // cols 300..319 stay zero
__device__ float g_Wc   [EMBv * EMBv];
__device__ float g_bc   [EMBv];

// ---------------- helpers -----------------------------------------------------
__device__ __forceinline__ float rna_tf32(float x) {
    uint32_t u; asm("cvt.rna.tf32.f32 %0, %1;" : "=r"(u) : "f"(x));
    return __uint_as_float(u);
}
__device__ __forceinline__ void mma_tf32(float* d, const float* a, const float* b) {
    asm volatile(
        "mma.sync.aligned.m16n8k8.row.col.f32.tf32.tf32.f32 "
        "{%0,%1,%2,%3}, {%4,%5,%6,%7}, {%8,%9}, {%0,%1,%2,%3};\n"
        : "+f"(d[0]), "+f"(d[1]), "+f"(d[2]), "+f"(d[3])
        : "r"(__float_as_uint(a[0])), "r"(__float_as_uint(a[1])),
          "r"(__float_as_uint(a[2])), "r"(__float_as_uint(a[3])),
          "r"(__float_as_uint(b[0])), "r"(__float_as_uint(b[1])));
}
__device__ __forceinline__ void cp16(uint32_t s, const void* g, int nbytes) {
    asm volatile("cp.async.cg.shared.global [%0], [%1], 16, %2;"
                 :: "r"(s), "l"(g), "r"(nbytes));
}
#define CP_COMMIT() asm volatile("cp.async.commit_group;" ::: "memory")
#define CP_WAIT2()  asm volatile("cp.async.wait_group 2;" ::: "memory")
#define CP_WAIT1()  asm volatile("cp.async.wait_group 1;" ::: "memory")
#define CP_WAIT0()  asm volatile("cp.async.wait_group 0;" ::: "memory")

__device__ __forceinline__ void stage_chunk(
    uint32_t base, int t, int c,
    const float* __restrict__ A, int lda, int aK4, int m0,
    const float* __restrict__ B, int ldb, int bK4, int bRows, int n0)
{
    uint32_t sA = base, sB = base + SBUF * 4;
#pragma unroll
    for (int it = 0; it < 4; it++) {
        int idx = it * 256 + t;
        int m = idx >> 3, p = idx & 7;
        int f4 = c * 8 + p;
        cp16(sA + (uint32_t)(m * LDS_ROW + p * 4) * 4,
             A + (size_t)(m0 + m) * lda + f4 * 4, (f4 < aK4) ? 16 : 0);
    }
#pragma unroll
    for (int it = 0; it < 4; it++) {
        int idx = it * 256 + t;
        int r = idx >> 3, p = idx & 7;
        int f4 = c * 8 + p;
        cp16(sB + (uint32_t)(r * LDS_ROW + p * 4) * 4,
             B + (size_t)(n0 + r) * ldb + f4 * 4,
             (f4 < bK4 && (n0 + r) < bRows) ? 16 : 0);
    }
}

__device__ __forceinline__ void compute_chunk(
    const float* __restrict__ As, const float* __restrict__ Bs,
    int wm, int wn, int g, int tid4, float acc[2][8][4])
{
#pragma unroll
    for (int ks = 0; ks < 4; ks++) {
        const int kb = ks * 8;
        float a[2][4];
#pragma unroll
        for (int i = 0; i < 2; i++) {
            int row = wm * 32 + i * 16 + g;
            a[i][0] = As[row * LDS_ROW + kb + tid4];
            a[i][1] = As[(row + 8) * LDS_ROW + kb + tid4];
            a[i][2] = As[row * LDS_ROW + kb + tid4 + 4];
            a[i][3] = As[(row + 8) * LDS_ROW + kb + tid4 + 4];
        }
        float b[8][2];
#pragma unroll
        for (int j = 0; j < 8; j++) {
            int col = wn * 64 + j * 8 + g;
            b[j][0] = Bs[col * LDS_ROW + kb + tid4];
            b[j][1] = Bs[col * LDS_ROW + kb + tid4 + 4];
        }
#pragma unroll
        for (int i = 0; i < 2; i++)
#pragma unroll
            for (int j = 0; j < 8; j++) mma_tf32(acc[i][j], a[i], b[j]);
    }
}

// ---------------- small kernels ------------------------------------------------
__global__ void round_wf_kernel(const float* __restrict__ Wf)
{
    int i = blockIdx.x * blockDim.x + threadIdx.x;
    if (i < EMBv * FEATv / 4) {
        float4 v = ((const float4*)Wf)[i];
        v.x = rna_tf32(v.x); v.y = rna_tf32(v.y); v.z = rna_tf32(v.z); v.w = rna_tf32(v.w);
        ((float4*)g_Wfr)[i] = v;
    }
}
__global__ void combine_kernel(const float* __restrict__ Wp, const float* __restrict__ bp,
                               const float* __restrict__ Wm, const float* __restrict__ bm)
{
    int i = blockIdx.x * blockDim.x + threadIdx.x;
    if (i < EMBv * EMBv) g_Wc[i] = rna_tf32(Wp[i] + EPSV * Wm[i]);
    if (i < EMBv)        g_bc[i] = bp[i] + EPSV * bm[i];
}
__global__ void eye_kernel(float* __restrict__ target)
{
    int i = blockIdx.x * blockDim.x + threadIdx.x;
    if (i < BB * BB) target[i] = ((i / BB) == (i % BB)) ? 1.0f : 0.0f;
}

// ---------------- pipelined tf32 GEMM: out = rna(A*B^T + epi), 3 stages -------
__global__ __launch_bounds__(256, 2) void mma_gemm_async(
    const float* __restrict__ A, int lda, int aK4,
    const float* __restrict__ B, int ldb, int bRows, int bK4,
    int nChunks, int mode, const float* __restrict__ bias,
    const float* __restrict__ wv, const int* __restrict__ label,
    float* __restrict__ out)
{
    extern __shared__ float smem[];
    const int m0 = blockIdx.y * 128;
    const int n0 = blockIdx.x * 128;
    const int t  = threadIdx.x;
    const int wid = t >> 5, lane = t & 31;
    const int wm = wid & 3, wn = wid >> 2;
    const int g = lane >> 2, tid4 = lane & 3;

    uint32_t sb = (uint32_t)__cvta_generic_to_shared(smem);

    float acc[2][8][4];
#pragma unroll
    for (int i = 0; i < 2; i++)
#pragma unroll
        for (int j = 0; j < 8; j++)
#pragma unroll
            for (int r = 0; r < 4; r++) acc[i][j][r] = 0.0f;

    stage_chunk(sb, t, 0, A, lda, aK4, m0, B, ldb, bK4, bRows, n0);
    CP_COMMIT();
    stage_chunk(sb + STAGE_F * 4, t, 1, A, lda, aK4, m0, B, ldb, bK4, bRows, n0);
    CP_COMMIT();

    for (int c = 0; c < nChunks; c++) {
        if (c + 2 < nChunks) { CP_WAIT1(); } else { CP_WAIT0(); }
        __syncthreads();
        const float* As = smem + (c % 3) * STAGE_F;
        compute_chunk(As, As + SBUF, wm, wn, g, tid4, acc);
        if (c + 2 < nChunks) {
            stage_chunk(sb + ((c + 2) % 3) * STAGE_F * 4, t, c + 2,
                        A, lda, aK4, m0, B, ldb, bK4, bRows, n0);
            CP_COMMIT();
        }
    }

#pragma unroll
    for (int i = 0; i < 2; i++) {
#pragma unroll
        for (int rh = 0; rh < 2; rh++) {
            int gm = m0 + wm * 32 + i * 16 + g + rh * 8;
            const float* wrow = (mode == 0) ? (wv + (size_t)label[gm] * EMBv) : nullptr;
#pragma unroll
            for (int j = 0; j < 8; j++) {
#pragma unroll
                for (int q = 0; q < 2; q++) {
                    int gn = n0 + wn * 64 + j * 8 + 2 * tid4 + q;
                    if (gn < EMBv) {
                        float v = acc[i][j][rh * 2 + q] + bias[gn];
                        if (mode == 0) v += wrow[gn];
                        out[(size_t)gm * KP + gn] = rna_tf32(v);
                    }
                }
            }
        }
    }
}

// ---------------- attmap: pipelined MMA + fused softmax/max/sum ---------------
#define CS_LD 129
__global__ __launch_bounds__(256, 2) void attmap_mma_async(
    float* __restrict__ logits, float* __restrict__ attsum,
    const int* __restrict__ num_query)
{
    extern __shared__ float smem[];
    const int m0 = blockIdx.y * 128;
    const int n0 = blockIdx.x * 128;
    const int t  = threadIdx.x;
    const int wid = t >> 5, lane = t & 31;
    const int wm = wid & 3, wn = wid >> 2;
    const int g = lane >> 2, tid4 = lane & 3;

    uint32_t sb = (uint32_t)__cvta_generic_to_shared(smem);

    float acc[2][8][4];
#pragma unroll
    for (int i = 0; i < 2; i++)
#pragma unroll
        for (int j = 0; j < 8; j++)
#pragma unroll
            for (int r = 0; r < 4; r++) acc[i][j][r] = 0.0f;

    const int NCH = KP / 32;
    stage_chunk(sb, t, 0, g_pembr, KP, KP / 4, m0, g_kemb, KP, KP / 4, BB * NKv, n0);
    CP_COMMIT();
    stage_chunk(sb + STAGE_F * 4, t, 1, g_pembr, KP, KP / 4, m0,
                g_kemb, KP, KP / 4, BB * NKv, n0);
    CP_COMMIT();

    for (int c = 0; c < NCH; c++) {
        if (c + 2 < NCH) { CP_WAIT1(); } else { CP_WAIT0(); }
        __syncthreads();
        const float* As = smem + (c % 3) * STAGE_F;
        compute_chunk(As, As + SBUF, wm, wn, g, tid4, acc);
        if (c + 2 < NCH) {
            stage_chunk(sb + ((c + 2) % 3) * STAGE_F * 4, t, c + 2,
                        g_pembr, KP, KP / 4, m0, g_kemb, KP, KP / 4, BB * NKv, n0);
            CP_COMMIT();
        }
    }
    __syncthreads();

    float* Cs = smem;
#pragma unroll
    for (int i = 0; i < 2; i++) {
#pragma unroll
        for (int rh = 0; rh < 2; rh++) {
            int row = wm * 32 + i * 16 + g + rh * 8;
#pragma unroll
            for (int j = 0; j < 8; j++) {
                int col = wn * 64 + j * 8 + 2 * tid4;
                Cs[row * CS_LD + col]     = acc[i][j][rh * 2 + 0];
                Cs[row * CS_LD + col + 1] = acc[i][j][rh * 2 + 1];
            }
        }
    }
    __syncthreads();

    const int bk = wid & 3, ah = wid >> 2;
    const int b = (m0 >> 5) + bk;
    const int a = (n0 >> 6) + ah;
    float* row = &Cs[(bk * 32 + lane) * CS_LD + ah * 64];

    float mx = -1e30f;
#pragma unroll
    for (int v = 0; v < 64; v++) mx = fmaxf(mx, row[v]);

    float s = mx;
#pragma unroll
    for (int o = 16; o; o >>= 1) s += __shfl_xor_sync(0xffffffffu, s, o);
    if (lane == 0) logits[b * BB + a] = s / (float)num_query[b];

    float se = 0.f;
#pragma unroll
    for (int v = 0; v < 64; v++) { float e = __expf(row[v] - mx); se += e; row[v] = e; }
    const float rinv = 1.0f / se;
#pragma unroll
    for (int v = 0; v < 64; v++) row[v] *= rinv;
    __syncthreads();

    {
        float s0 = 0.f, s1 = 0.f;
        const float* base = &Cs[(bk * 32) * CS_LD + ah * 64];
#pragma unroll
        for (int q = 0; q < 32; q++) {
            s0 += base[q * CS_LD + lane];
            s1 += base[q * CS_LD + lane + 32];
        }
        attsum[((size_t)b * BB + a) * NKv + lane]      = s0;
        attsum[((size_t)b * BB + a) * NKv + lane + 32] = s1;
    }
}

// ---------------- p0 via MMA: one CTA per b -----------------------------------
// S[384,64] = q_emb(gathered) @ kemb[b]^T, fused word-attn softmaxes -> p0.
#define KSB_LD 324                      // (4*col + k) mod 32 bijective
#define PA_LD  36
#define PABUF  (128 * PA_LD)            // one A stage (floats)
#define P0_SMEM_F (64 * KSB_LD + 3 * PABUF + 384 + 384 + 384)
#define P0_SMEM_BYTES (P0_SMEM_F * 4)

__global__ __launch_bounds__(256) void p0_mma_kernel(const int* __restrict__ query,
                                                     const float* __restrict__ wv)
{
    extern __shared__ float ps[];
    float* Ks    = ps;                       // [64][KSB_LD]
    float* Ab    = Ks + 64 * KSB_LD;         // 3 x [128][PA_LD]
    float* qma   = Ab + 3 * PABUF;           // [384]
    float* qnorm = qma + 384;                // [384]
    int*   qi    = (int*)(qnorm + 384);      // [384]

    const int b = blockIdx.x;
    const int t = threadIdx.x;
    const int wid = t >> 5, lane = t & 31;
    const int g = lane >> 2, tid4 = lane & 3;

    uint32_t sb = (uint32_t)__cvta_generic_to_shared(ps);
    const uint32_t ks_sb = sb;
    const uint32_t ab_sb = sb + 64 * KSB_LD * 4;

    // qidx
    for (int idx = t; idx < 384; idx += 256)
        qi[idx] = query[b * 384 + idx];
    __syncthreads();

    // stage Ks: kemb[b] 64 rows x 80 float4 (zeros beyond col 300 already)
    {
        const float* kb = g_kemb + (size_t)b * NKv * KP;
        for (int idx = t; idx < 64 * 80; idx += 256) {
            int r = idx / 80, f4 = idx % 80;
            cp16(ks_sb + (uint32_t)(r * KSB_LD + f4 * 4) * 4,
                 kb + (size_t)r * KP + f4 * 4, 16);
        }
        CP_COMMIT();
    }

    // A chunk stager: chunk cc (0..29): msub = cc/10, kc = cc%10
    auto stage_a = [&](int cc, int buf) {
        const int msub = cc / 10, kc = cc % 10;
        uint32_t base = ab_sb + (uint32_t)buf * PABUF * 4;
#pragma unroll
        for (int it = 0; it < 4; it++) {
            int idx = it * 256 + t;
            int row = idx >> 3, p = idx & 7;
            int f4 = kc * 8 + p;
            int ridx = msub * 128 + row;
            cp16(base + (uint32_t)(row * PA_LD + p * 4) * 4,
                 wv + (size_t)qi[ridx] * EMBv + f4 * 4,
                 (f4 < 75) ? 16 : 0);
        }
    };

    stage_a(0, 0); CP_COMMIT();
    stage_a(1, 1); CP_COMMIT();

    float acc[8][4];
#pragma unroll
    for (int j = 0; j < 8; j++)
#pragma unroll
        for (int r = 0; r < 4; r++) acc[j][r] = 0.0f;

    const float scale = rsqrtf((float)EMBv);

    for (int cc = 0; cc < 30; cc++) {
        if (cc + 2 < 30) { stage_a(cc + 2, (cc + 2) % 3); CP_COMMIT(); }
        if (cc < 28)      { CP_WAIT2(); }
        else if (cc == 28){ CP_WAIT1(); }
        else              { CP_WAIT0(); }
        __syncthreads();

        const float* As = Ab + (cc % 3) * PABUF;
        const int kc = cc % 10;
        const float* Bk = Ks + kc * 32;
#pragma unroll
        for (int ks = 0; ks < 4; ks++) {
            const int kb = ks * 8;
            float a[4];
            {
                int row = wid * 16 + g;
                a[0] = As[row * PA_LD + kb + tid4];
                a[1] = As[(row + 8) * PA_LD + kb + tid4];
                a[2] = As[row * PA_LD + kb + tid4 + 4];
                a[3] = As[(row + 8) * PA_LD + kb + tid4 + 4];
            }
            float bf[8][2];
#pragma unroll
            for (int j = 0; j < 8; j++) {
                int col = j * 8 + g;
                bf[j][0] = Bk[col * KSB_LD + kb + tid4];
                bf[j][1] = Bk[col * KSB_LD + kb + tid4 + 4];
            }
#pragma unroll
            for (int j = 0; j < 8; j++) mma_tf32(acc[j], a, bf[j]);
        }

        if (kc == 9) {
            // row softmax-over-k: qma = 1/sumexp per row
            const int msub = cc / 10;
#pragma unroll
            for (int rh = 0; rh < 2; rh++) {
                float mx = -1e30f;
#pragma unroll
                for (int j = 0; j < 8; j++) {
                    mx = fmaxf(mx, acc[j][rh * 2]);
                    mx = fmaxf(mx, acc[j][rh * 2 + 1]);
                }
                mx = fmaxf(mx, __shfl_xor_sync(0xffffffffu, mx, 1));
                mx = fmaxf(mx, __shfl_xor_sync(0xffffffffu, mx, 2));
                float mxs = mx * scale;
                float se = 0.f;
#pragma unroll
                for (int j = 0; j < 8; j++) {
                    se += __expf(acc[j][rh * 2] * scale - mxs);
                    se += __expf(acc[j][rh * 2 + 1] * scale - mxs);
                }
                se += __shfl_xor_sync(0xffffffffu, se, 1);
                se += __shfl_xor_sync(0xffffffffu, se, 2);
                if (tid4 == 0)
                    qma[msub * 128 + wid * 16 + rh * 8 + g] = 1.0f / se;
            }
#pragma unroll
            for (int j = 0; j < 8; j++)
#pragma unroll
                for (int r = 0; r < 4; r++) acc[j][r] = 0.0f;
        }
    }
    __syncthreads();

    // word softmax over 12 words per q (threads 0..31)
    if (t < 32) {
        const int q = t;
        float m2 = -1e30f;
#pragma unroll
        for (int w = 0; w < NWv; w++) m2 = fmaxf(m2, qma[q * NWv + w]);
        float s2 = 0.f;
        float e[NWv];
#pragma unroll
        for (int w = 0; w < NWv; w++) { e[w] = __expf(qma[q * NWv + w] - m2); s2 += e[w]; }
        float inv = 1.0f / s2;
#pragma unroll
        for (int w = 0; w < NWv; w++) qnorm[q * NWv + w] = e[w] * inv;
    }
    __syncthreads();

    // p0[b,q,d] = rna( sum_w qnorm * wv[qidx] )
    for (int idx = t; idx < NQv * EMBv; idx += 256) {
        int q = idx / EMBv, d = idx % EMBv;
        float s = 0.f;
#pragma unroll
        for (int w = 0; w < NWv; w++)
            s += qnorm[q * NWv + w] * wv[(size_t)qi[q * NWv + w] * EMBv + d];
        g_p0[(size_t)(b * NQv + q) * EMBv + d] = rna_tf32(s);
    }
}

// ---------------- launch ------------------------------------------------------
extern "C" void kernel_launch(void* const* d_in, const int* in_sizes, int n_in,
                              void* d_out, int out_size)
{
    const int*   query     = (const int*)  d_in[1];
    const int*   label     = (const int*)  d_in[2];
    const float* feature   = (const float*)d_in[3];
    const int*   num_query = (const int*)  d_in[7];
    const float* wv        = (const float*)d_in[8];
    const float* Wp        = (const float*)d_in[9];
    const float* bp        = (const float*)d_in[10];
    const float* Wm        = (const float*)d_in[11];
    const float* bm        = (const float*)d_in[12];
    const float* Wf        = (const float*)d_in[13];
    const float* bf        = (const float*)d_in[14];

    float* out    = (float*)d_out;
    float* logits = out;
    float* target = out + BB * BB;
    float* attsum = out + 2 * BB * BB;

    static int smem_set = 0;
    if (!smem_set) {
        cudaFuncSetAttribute(mma_gemm_async,
                             cudaFuncAttributeMaxDynamicSharedMemorySize, SMEM_BYTES);
        cudaFuncSetAttribute(attmap_mma_async,
                             cudaFuncAttributeMaxDynamicSharedMemorySize, SMEM_BYTES);
        cudaFuncSetAttribute(p0_mma_kernel,
                             cudaFuncAttributeMaxDynamicSharedMemorySize, P0_SMEM_BYTES);
        smem_set = 1;
    }

    float* d_Wfr; cudaGetSymbolAddress((void**)&d_Wfr, g_Wfr);
    float* d_Wc;  cudaGetSymbolAddress((void**)&d_Wc,  g_Wc);
    float* d_bc;  cudaGetSymbolAddress((void**)&d_bc,  g_bc);
    float* d_p0;  cudaGetSymbolAddress((void**)&d_p0,  g_p0);
    float* d_ke;  cudaGetSymbolAddress((void**)&d_ke,  g_kemb);
    float* d_pe;  cudaGetSymbolAddress((void**)&d_pe,  g_pembr);

    round_wf_kernel<<<(EMBv * FEATv / 4 + 255) / 256, 256>>>(Wf);
    combine_kernel<<<(EMBv * EMBv + 255) / 256, 256>>>(Wp, bp, Wm, bm);

    // k_emb = rna( feature @ Wf^T + wv[label] + bf )  [8192 x 300 x 2048]
    mma_gemm_async<<<dim3(3, 64), 256, SMEM_BYTES>>>(
        feature, FEATv, FEATv / 4, d_Wfr, FEATv, EMBv, FEATv / 4,
        FEATv / 32, 0, bf, wv, label, d_ke);

    // p0 via per-b MMA
    p0_mma_kernel<<<BB, 256, P0_SMEM_BYTES>>>(query, wv);

    // p_emb = rna( p0 @ Wc^T + bc )  [4096 x 300 x 300]
    mma_gemm_async<<<dim3(3, 32), 256, SMEM_BYTES>>>(
        d_p0, EMBv, 75, d_Wc, EMBv, EMBv, 75,
        10, 1, d_bc, nullptr, nullptr, d_pe);

    // attmap + fused softmax/max/sum  [4096 x 8192 x 320]
    attmap_mma_async<<<dim3(64, 32), 256, SMEM_BYTES>>>(logits, attsum, num_query);

    eye_kernel<<<(BB * BB + 255) / 256, 256>>>(target);
}